// round 12
// baseline (speedup 1.0000x reference)
#include <cuda_runtime.h>
#include <cuda_bf16.h>
#include <math.h>

// Problem constants (fixed shapes per reference)
#define NN    100000      // total nodes
#define BB    50          // graphs
#define NPG   2000        // nodes per graph
#define FF    64          // input features
#define HH    64          // hidden
#define EE    1600000     // edges
#define EPG   (EE / BB)   // 32000 edges per graph (graph-contiguous by construction)
#define NBANDS 3
#define NZF   2400000     // framelet nnz
#define NZPG  (NZF / BB)  // 48000 nz per graph (graph-contiguous)
#define NCC   10          // classes

// ---------------- static scratch (no allocation allowed) ----------------
__device__ __align__(256) float g_bufA[(size_t)NN * HH];
__device__ __align__(256) float g_bufB[(size_t)NN * HH];
__device__ __align__(256) float g_dinv[NN];
__device__ __align__(256) int2  g_offcnt[NN];     // {csr offset, degree}
__device__ __align__(256) int   g_col[EE];
__device__ __align__(256) float g_w[(size_t)NN * NBANDS];
__device__ __align__(256) float g_xp[BB * NBANDS * HH];

// ---------------- streams/events for intra-graph parallelism ----------------
struct StreamPack {
    cudaStream_t sB = nullptr, sC = nullptr;
    cudaEvent_t  ev0 = nullptr, evD = nullptr, evB = nullptr, evC = nullptr;
    bool ok = false;
    StreamPack() {
        if (cudaStreamCreateWithFlags(&sB, cudaStreamNonBlocking) != cudaSuccess) return;
        if (cudaStreamCreateWithFlags(&sC, cudaStreamNonBlocking) != cudaSuccess) return;
        if (cudaEventCreateWithFlags(&ev0, cudaEventDisableTiming) != cudaSuccess) return;
        if (cudaEventCreateWithFlags(&evD, cudaEventDisableTiming) != cudaSuccess) return;
        if (cudaEventCreateWithFlags(&evB, cudaEventDisableTiming) != cudaSuccess) return;
        if (cudaEventCreateWithFlags(&evC, cudaEventDisableTiming) != cudaSuccess) return;
        ok = true;
    }
};
static StreamPack g_sp;

// ---------------- build1: per-graph hist + scan -> g_offcnt, g_dinv ----------
__global__ void __launch_bounds__(1024, 1)
build1_kernel(const int* __restrict__ erow) {
    __shared__ int hcnt[NPG];        // 8 KB
    __shared__ int warp_part[32];
    __shared__ int warp_off[32];
    int g = blockIdx.x;
    int t = threadIdx.x;
    int lane = t & 31, warp = t >> 5;
    int node0 = g * NPG;
    int ebase = g * EPG;

    for (int i = t; i < NPG; i += 1024) hcnt[i] = 0;
    __syncthreads();

    for (int i = t * 4; i < EPG; i += 1024 * 4) {
        int4 r = *(const int4*)(erow + ebase + i);
        atomicAdd(&hcnt[r.x - node0], 1);
        atomicAdd(&hcnt[r.y - node0], 1);
        atomicAdd(&hcnt[r.z - node0], 1);
        atomicAdd(&hcnt[r.w - node0], 1);
    }
    __syncthreads();

    int c0 = 0, c1 = 0, s = 0;
    if (t < NPG / 2) {
        c0 = hcnt[2 * t];
        c1 = hcnt[2 * t + 1];
        s = c0 + c1;
    }
    int incl = s;
    for (int d = 1; d < 32; d <<= 1) {
        int u = __shfl_up_sync(0xffffffff, incl, d);
        if (lane >= d) incl += u;
    }
    if (lane == 31) warp_part[warp] = incl;
    __syncthreads();
    if (t < 32) {
        int x = warp_part[t];
        int wincl = x;
        for (int d = 1; d < 32; d <<= 1) {
            int u = __shfl_up_sync(0xffffffff, wincl, d);
            if (t >= d) wincl += u;
        }
        warp_off[t] = wincl - x;
    }
    __syncthreads();
    if (t < NPG / 2) {
        int excl = (incl - s) + warp_off[warp];
        int base = ebase + excl;
        int r = node0 + 2 * t;
        g_offcnt[r]     = make_int2(base, c0);
        g_offcnt[r + 1] = make_int2(base + c0, c1);
        g_dinv[r]     = rsqrtf((float)(c0 + 1));
        g_dinv[r + 1] = rsqrtf((float)(c1 + 1));
    }
}

// ---------------- build2: per-graph scatter with smem counters ---------------
__global__ void __launch_bounds__(1024, 1)
build2_kernel(const int* __restrict__ erow, const int* __restrict__ ecol) {
    __shared__ int cur[NPG];         // 8 KB
    int g = blockIdx.x;
    int t = threadIdx.x;
    int node0 = g * NPG;
    int ebase = g * EPG;

    for (int i = t; i < NPG; i += 1024) cur[i] = g_offcnt[node0 + i].x;
    __syncthreads();

    for (int i = t * 4; i < EPG; i += 1024 * 4) {
        int4 r = *(const int4*)(erow + ebase + i);
        int4 c = *(const int4*)(ecol + ebase + i);
        int p0 = atomicAdd(&cur[r.x - node0], 1);
        int p1 = atomicAdd(&cur[r.y - node0], 1);
        int p2 = atomicAdd(&cur[r.z - node0], 1);
        int p3 = atomicAdd(&cur[r.w - node0], 1);
        g_col[p0] = c.x;
        g_col[p1] = c.y;
        g_col[p2] = c.z;
        g_col[p3] = c.w;
    }
}

// ---------------- GEMM: Y[r] = dinv[r] * (X[r] @ W) ----------------
__global__ void gemm64_kernel(const float* __restrict__ X, const float* __restrict__ W,
                              float* __restrict__ Y, int M) {
    __shared__ float Ws[64 * 64];
    __shared__ float Xs[64][65];
    int t = threadIdx.x;
    int row0 = blockIdx.x * 64;
    int rows = min(64, M - row0);

    for (int i = t; i < 1024; i += 256)
        ((float4*)Ws)[i] = ((const float4*)W)[i];
    for (int i = t; i < rows * 64; i += 256) {
        int r = i >> 6, c = i & 63;
        Xs[r][c] = X[(size_t)(row0 + r) * 64 + c];
    }
    __syncthreads();

    int r = t & 63;
    int cg = t >> 6;            // 0..3 -> 16 columns each
    if (r < rows) {
        float acc[16];
#pragma unroll
        for (int j = 0; j < 16; j++) acc[j] = 0.0f;
#pragma unroll 8
        for (int k = 0; k < 64; k++) {
            float a = Xs[r][k];
            const float4* wr = (const float4*)(Ws + k * 64 + cg * 16);
#pragma unroll
            for (int j = 0; j < 4; j++) {
                float4 w = wr[j];
                acc[4 * j + 0] += a * w.x;
                acc[4 * j + 1] += a * w.y;
                acc[4 * j + 2] += a * w.z;
                acc[4 * j + 3] += a * w.w;
            }
        }
        float dv = g_dinv[row0 + r];
        float4* yp = (float4*)(Y + (size_t)(row0 + r) * 64 + cg * 16);
#pragma unroll
        for (int j = 0; j < 4; j++)
            yp[j] = make_float4(dv * acc[4 * j], dv * acc[4 * j + 1],
                                dv * acc[4 * j + 2], dv * acc[4 * j + 3]);
    }
}

// ---------------- GCN layer-1 aggregation + bias + relu (writes hout) --------
__global__ void agg_kernel(const float* __restrict__ hin, float* __restrict__ hout,
                           const float* __restrict__ bias) {
    int warp = (blockIdx.x * blockDim.x + threadIdx.x) >> 5;
    if (warp >= NN) return;
    int lane = threadIdx.x & 31;
    int grp  = lane >> 4;        // 0 or 1
    int fo   = lane & 15;        // float4 slot within row
    int row = warp;
    int2 oc = g_offcnt[row];
    int off = oc.x;
    int cnt = oc.y;
    float4 a0 = make_float4(0.f, 0.f, 0.f, 0.f);
    float4 a1 = make_float4(0.f, 0.f, 0.f, 0.f);
    int k = grp;
    for (; k + 2 < cnt; k += 4) {
        int c0 = __ldg(&g_col[off + k]);
        int c1 = __ldg(&g_col[off + k + 2]);
        float4 v0 = *(const float4*)(hin + (size_t)c0 * 64 + fo * 4);
        float4 v1 = *(const float4*)(hin + (size_t)c1 * 64 + fo * 4);
        a0.x += v0.x; a0.y += v0.y; a0.z += v0.z; a0.w += v0.w;
        a1.x += v1.x; a1.y += v1.y; a1.z += v1.z; a1.w += v1.w;
    }
    for (; k < cnt; k += 2) {
        int c = __ldg(&g_col[off + k]);
        float4 v = *(const float4*)(hin + (size_t)c * 64 + fo * 4);
        a0.x += v.x; a0.y += v.y; a0.z += v.z; a0.w += v.w;
    }
    if (grp == 0) {
        float4 v = *(const float4*)(hin + (size_t)row * 64 + fo * 4);
        a0.x += v.x; a0.y += v.y; a0.z += v.z; a0.w += v.w;
    }
    a0.x += a1.x; a0.y += a1.y; a0.z += a1.z; a0.w += a1.w;
    a0.x += __shfl_down_sync(0xffffffff, a0.x, 16);
    a0.y += __shfl_down_sync(0xffffffff, a0.y, 16);
    a0.z += __shfl_down_sync(0xffffffff, a0.z, 16);
    a0.w += __shfl_down_sync(0xffffffff, a0.w, 16);
    if (grp == 0) {
        float di = g_dinv[row];
        float4 b = *(const float4*)(bias + fo * 4);
        float4 o;
        o.x = fmaxf(di * a0.x + b.x, 0.f);
        o.y = fmaxf(di * a0.y + b.y, 0.f);
        o.z = fmaxf(di * a0.z + b.z, 0.f);
        o.w = fmaxf(di * a0.w + b.w, 0.f);
        *(float4*)(hout + (size_t)row * 64 + fo * 4) = o;
    }
}

// ---------------- GCN layer-2 aggregation FUSED with band pooling ------------
// Identical gather; instead of writing h2, accumulates w[row][band]*h2[row][f]
// into per-block smem xp (8 rows/block, 2000 % 8 == 0 -> one graph per block),
// then flushes to g_xp with global atomics. No 25.6MB write, no tail re-read.
__global__ void agg_pool_kernel(const float* __restrict__ hin,
                                const float* __restrict__ bias) {
    __shared__ float xp[NBANDS * HH];   // 192 floats
    int t = threadIdx.x;
    int warp = (blockIdx.x * blockDim.x + t) >> 5;
    int lane = t & 31;
    int grp  = lane >> 4;
    int fo   = lane & 15;
    if (t < NBANDS * HH) xp[t] = 0.0f;
    __syncthreads();

    if (warp < NN) {
        int row = warp;
        int2 oc = g_offcnt[row];
        int off = oc.x;
        int cnt = oc.y;
        float4 a0 = make_float4(0.f, 0.f, 0.f, 0.f);
        float4 a1 = make_float4(0.f, 0.f, 0.f, 0.f);
        int k = grp;
        for (; k + 2 < cnt; k += 4) {
            int c0 = __ldg(&g_col[off + k]);
            int c1 = __ldg(&g_col[off + k + 2]);
            float4 v0 = *(const float4*)(hin + (size_t)c0 * 64 + fo * 4);
            float4 v1 = *(const float4*)(hin + (size_t)c1 * 64 + fo * 4);
            a0.x += v0.x; a0.y += v0.y; a0.z += v0.z; a0.w += v0.w;
            a1.x += v1.x; a1.y += v1.y; a1.z += v1.z; a1.w += v1.w;
        }
        for (; k < cnt; k += 2) {
            int c = __ldg(&g_col[off + k]);
            float4 v = *(const float4*)(hin + (size_t)c * 64 + fo * 4);
            a0.x += v.x; a0.y += v.y; a0.z += v.z; a0.w += v.w;
        }
        if (grp == 0) {
            float4 v = *(const float4*)(hin + (size_t)row * 64 + fo * 4);
            a0.x += v.x; a0.y += v.y; a0.z += v.z; a0.w += v.w;
        }
        a0.x += a1.x; a0.y += a1.y; a0.z += a1.z; a0.w += a1.w;
        a0.x += __shfl_down_sync(0xffffffff, a0.x, 16);
        a0.y += __shfl_down_sync(0xffffffff, a0.y, 16);
        a0.z += __shfl_down_sync(0xffffffff, a0.z, 16);
        a0.w += __shfl_down_sync(0xffffffff, a0.w, 16);
        if (grp == 0) {
            float di = g_dinv[row];
            float4 b = *(const float4*)(bias + fo * 4);
            float4 o;
            o.x = fmaxf(di * a0.x + b.x, 0.f);
            o.y = fmaxf(di * a0.y + b.y, 0.f);
            o.z = fmaxf(di * a0.z + b.z, 0.f);
            o.w = fmaxf(di * a0.w + b.w, 0.f);
            // band-weighted accumulation into block-local xp
            const float* wp = g_w + (size_t)row * NBANDS;
            float w0 = wp[0], w1 = wp[1], w2 = wp[2];
            int f = fo * 4;
            atomicAdd(&xp[f + 0], w0 * o.x);
            atomicAdd(&xp[f + 1], w0 * o.y);
            atomicAdd(&xp[f + 2], w0 * o.z);
            atomicAdd(&xp[f + 3], w0 * o.w);
            atomicAdd(&xp[64 + f + 0], w1 * o.x);
            atomicAdd(&xp[64 + f + 1], w1 * o.y);
            atomicAdd(&xp[64 + f + 2], w1 * o.z);
            atomicAdd(&xp[64 + f + 3], w1 * o.w);
            atomicAdd(&xp[128 + f + 0], w2 * o.x);
            atomicAdd(&xp[128 + f + 1], w2 * o.y);
            atomicAdd(&xp[128 + f + 2], w2 * o.z);
            atomicAdd(&xp[128 + f + 3], w2 * o.w);
        }
    }
    __syncthreads();
    // one graph per block (8 rows, 2000 % 8 == 0)
    int g = (blockIdx.x * (blockDim.x / 32)) / NPG;
    if (t < NBANDS * HH) atomicAdd(&g_xp[g * (NBANDS * HH) + t], xp[t]);
}

// ---------------- framelet node-band weights (independent of GCN path) -------
__global__ void __launch_bounds__(1024, 1)
frame_kernel(const int* __restrict__ frow, const int* __restrict__ fcol,
             const float* __restrict__ fval, const int* __restrict__ dindex) {
    __shared__ float ws[NPG * NBANDS];   // 24 KB
    int g = blockIdx.x;
    int t = threadIdx.x;
    int node0 = g * NPG;
    for (int i = t; i < NPG * NBANDS; i += 1024) ws[i] = 0.0f;
    __syncthreads();
    int base = g * NZPG;
    for (int i = t; i < NZPG; i += 1024) {
        int k = base + i;
        int band = __ldg(&dindex[frow[k]]);
        int c = fcol[k] - node0;
        atomicAdd(&ws[c * NBANDS + band], fval[k]);
    }
    __syncthreads();
    float* dst = g_w + (size_t)g * NPG * NBANDS;
    for (int i = t; i < (NPG * NBANDS) / 4; i += 1024)
        ((float4*)dst)[i] = ((const float4*)ws)[i];
}

// ---------------- MLP head ----------------
__global__ void head_kernel(const float* __restrict__ fcW1, const float* __restrict__ fcb1,
                            const float* __restrict__ fcW2, const float* __restrict__ fcb2,
                            float* __restrict__ out) {
    __shared__ float xs[NBANDS * HH];
    __shared__ float hid[HH];
    int g = blockIdx.x;
    int t = threadIdx.x;                // 64 threads
    for (int i = t; i < NBANDS * HH; i += 64)
        xs[i] = g_xp[g * (NBANDS * HH) + i];
    __syncthreads();
    float acc = fcb1[t];
#pragma unroll 8
    for (int k = 0; k < NBANDS * HH; k++)
        acc += xs[k] * fcW1[k * HH + t];
    hid[t] = fmaxf(acc, 0.0f);
    __syncthreads();
    if (t < NCC) {
        float o = fcb2[t];
#pragma unroll 8
        for (int k = 0; k < HH; k++)
            o += hid[k] * fcW2[k * NCC + t];
        out[g * NCC + t] = o;
    }
}

// ---------------- launch ----------------
extern "C" void kernel_launch(void* const* d_in, const int* in_sizes, int n_in,
                              void* d_out, int out_size) {
    const float* x         = (const float*)d_in[0];
    const int*   ei        = (const int*)  d_in[1];   // [2, E]: rows then cols
    const int*   frow      = (const int*)  d_in[3];
    const int*   fcol      = (const int*)  d_in[4];
    const float* fval      = (const float*)d_in[5];
    const int*   dindex    = (const int*)  d_in[6];
    const float* W1        = (const float*)d_in[8];
    const float* b1        = (const float*)d_in[9];
    const float* W2        = (const float*)d_in[10];
    const float* b2        = (const float*)d_in[11];
    const float* fcW1      = (const float*)d_in[12];
    const float* fcb1      = (const float*)d_in[13];
    const float* fcW2      = (const float*)d_in[14];
    const float* fcb2      = (const float*)d_in[15];
    float* out = (float*)d_out;

    const int* erow = ei;
    const int* ecol = ei + EE;

    float* bufA; cudaGetSymbolAddress((void**)&bufA, g_bufA);
    float* bufB; cudaGetSymbolAddress((void**)&bufB, g_bufB);
    float* xp;   cudaGetSymbolAddress((void**)&xp,   g_xp);

    bool par = g_sp.ok;

    if (par) {
        // framelet weights are input-only: run from t=0 on sC
        cudaEventRecord(g_sp.ev0, 0);
        cudaStreamWaitEvent(g_sp.sC, g_sp.ev0, 0);
        frame_kernel<<<BB, 1024, 0, g_sp.sC>>>(frow, fcol, fval, dindex);
        cudaEventRecord(g_sp.evC, g_sp.sC);
    }

    cudaMemsetAsync(xp, 0, BB * NBANDS * HH * sizeof(float), 0);

    // CSR build: per-graph hist+scan (writes offcnt/dinv), then smem scatter
    build1_kernel<<<BB, 1024>>>(erow);

    if (par) {
        // dinv ready -> gemm1 (dinv epilogue) overlaps build2
        cudaEventRecord(g_sp.evD, 0);
        cudaStreamWaitEvent(g_sp.sB, g_sp.evD, 0);
        gemm64_kernel<<<(NN + 63) / 64, 256, 0, g_sp.sB>>>(x, W1, bufA, NN);
        cudaEventRecord(g_sp.evB, g_sp.sB);
    }

    build2_kernel<<<BB, 1024>>>(erow, ecol);

    if (par) {
        cudaStreamWaitEvent(0, g_sp.evB, 0);   // join gemm1
    } else {
        gemm64_kernel<<<(NN + 63) / 64, 256>>>(x, W1, bufA, NN);
    }

    // GCN layer 1 aggregation
    agg_kernel<<<(NN * 32 + 255) / 256, 256>>>(bufA, bufB, b1);

    // GCN layer 2 GEMM
    gemm64_kernel<<<(NN + 63) / 64, 256>>>(bufB, W2, bufA, NN);

    if (par) {
        cudaStreamWaitEvent(0, g_sp.evC, 0);   // join framelet weights (needed by fused pool)
    } else {
        frame_kernel<<<BB, 1024>>>(frow, fcol, fval, dindex);
    }

    // GCN layer 2 aggregation fused with band pooling
    agg_pool_kernel<<<(NN * 32 + 255) / 256, 256>>>(bufA, b2);

    // MLP head
    head_kernel<<<BB, 64>>>(fcW1, fcb1, fcW2, fcb2, out);
}

// round 14
// speedup vs baseline: 1.0469x; 1.0469x over previous
#include <cuda_runtime.h>
#include <cuda_bf16.h>
#include <math.h>

// Problem constants (fixed shapes per reference)
#define NN    100000      // total nodes
#define BB    50          // graphs
#define NPG   2000        // nodes per graph
#define FF    64          // input features
#define HH    64          // hidden
#define EE    1600000     // edges
#define EPG   (EE / BB)   // 32000 edges per graph (graph-contiguous by construction)
#define NBANDS 3
#define NZF   2400000     // framelet nnz
#define NZPG  (NZF / BB)  // 48000 nz per graph (graph-contiguous)
#define NCC   10          // classes
#define HALFN (NN / 2)    // 50000 rows per chain (25 graphs)

// ---------------- static scratch (no allocation allowed) ----------------
__device__ __align__(256) float g_bufA[(size_t)NN * HH];
__device__ __align__(256) float g_bufB[(size_t)NN * HH];
__device__ __align__(256) float g_dinv[NN];
__device__ __align__(256) int2  g_offcnt[NN];     // {csr offset, degree}
__device__ __align__(256) int   g_col[EE];
__device__ __align__(256) float g_w[(size_t)NN * NBANDS];

// ---------------- streams/events ----------------
struct StreamPack {
    cudaStream_t sB = nullptr, sC = nullptr;
    cudaEvent_t  ev0 = nullptr, evD = nullptr, evB = nullptr, evC = nullptr;
    cudaEvent_t  evS = nullptr, evE = nullptr;
    bool ok = false;
    StreamPack() {
        if (cudaStreamCreateWithFlags(&sB, cudaStreamNonBlocking) != cudaSuccess) return;
        if (cudaStreamCreateWithFlags(&sC, cudaStreamNonBlocking) != cudaSuccess) return;
        if (cudaEventCreateWithFlags(&ev0, cudaEventDisableTiming) != cudaSuccess) return;
        if (cudaEventCreateWithFlags(&evD, cudaEventDisableTiming) != cudaSuccess) return;
        if (cudaEventCreateWithFlags(&evB, cudaEventDisableTiming) != cudaSuccess) return;
        if (cudaEventCreateWithFlags(&evC, cudaEventDisableTiming) != cudaSuccess) return;
        if (cudaEventCreateWithFlags(&evS, cudaEventDisableTiming) != cudaSuccess) return;
        if (cudaEventCreateWithFlags(&evE, cudaEventDisableTiming) != cudaSuccess) return;
        ok = true;
    }
};
static StreamPack g_sp;

// ---------------- build1: per-graph hist + scan -> g_offcnt, g_dinv ----------
__global__ void __launch_bounds__(1024, 1)
build1_kernel(const int* __restrict__ erow) {
    __shared__ int hcnt[NPG];        // 8 KB
    __shared__ int warp_part[32];
    __shared__ int warp_off[32];
    int g = blockIdx.x;
    int t = threadIdx.x;
    int lane = t & 31, warp = t >> 5;
    int node0 = g * NPG;
    int ebase = g * EPG;

    for (int i = t; i < NPG; i += 1024) hcnt[i] = 0;
    __syncthreads();

    for (int i = t * 4; i < EPG; i += 1024 * 4) {
        int4 r = *(const int4*)(erow + ebase + i);
        atomicAdd(&hcnt[r.x - node0], 1);
        atomicAdd(&hcnt[r.y - node0], 1);
        atomicAdd(&hcnt[r.z - node0], 1);
        atomicAdd(&hcnt[r.w - node0], 1);
    }
    __syncthreads();

    int c0 = 0, c1 = 0, s = 0;
    if (t < NPG / 2) {
        c0 = hcnt[2 * t];
        c1 = hcnt[2 * t + 1];
        s = c0 + c1;
    }
    int incl = s;
    for (int d = 1; d < 32; d <<= 1) {
        int u = __shfl_up_sync(0xffffffff, incl, d);
        if (lane >= d) incl += u;
    }
    if (lane == 31) warp_part[warp] = incl;
    __syncthreads();
    if (t < 32) {
        int x = warp_part[t];
        int wincl = x;
        for (int d = 1; d < 32; d <<= 1) {
            int u = __shfl_up_sync(0xffffffff, wincl, d);
            if (t >= d) wincl += u;
        }
        warp_off[t] = wincl - x;
    }
    __syncthreads();
    if (t < NPG / 2) {
        int excl = (incl - s) + warp_off[warp];
        int base = ebase + excl;
        int r = node0 + 2 * t;
        g_offcnt[r]     = make_int2(base, c0);
        g_offcnt[r + 1] = make_int2(base + c0, c1);
        g_dinv[r]     = rsqrtf((float)(c0 + 1));
        g_dinv[r + 1] = rsqrtf((float)(c1 + 1));
    }
}

// ---------------- build2: per-graph scatter with smem counters ---------------
__global__ void __launch_bounds__(1024, 1)
build2_kernel(const int* __restrict__ erow, const int* __restrict__ ecol) {
    __shared__ int cur[NPG];         // 8 KB
    int g = blockIdx.x;
    int t = threadIdx.x;
    int node0 = g * NPG;
    int ebase = g * EPG;

    for (int i = t; i < NPG; i += 1024) cur[i] = g_offcnt[node0 + i].x;
    __syncthreads();

    for (int i = t * 4; i < EPG; i += 1024 * 4) {
        int4 r = *(const int4*)(erow + ebase + i);
        int4 c = *(const int4*)(ecol + ebase + i);
        int p0 = atomicAdd(&cur[r.x - node0], 1);
        int p1 = atomicAdd(&cur[r.y - node0], 1);
        int p2 = atomicAdd(&cur[r.z - node0], 1);
        int p3 = atomicAdd(&cur[r.w - node0], 1);
        g_col[p0] = c.x;
        g_col[p1] = c.y;
        g_col[p2] = c.z;
        g_col[p3] = c.w;
    }
}

// ---------------- GEMM: Y[r] = dinv[r] * (X[r] @ W) on rows [row0,row0+nr) ---
__global__ void gemm64_kernel(const float* __restrict__ X, const float* __restrict__ W,
                              float* __restrict__ Y, int row0, int nr) {
    __shared__ float Ws[64 * 64];
    __shared__ float Xs[64][65];
    int t = threadIdx.x;
    int rbase = row0 + blockIdx.x * 64;
    int rows = min(64, row0 + nr - rbase);

    for (int i = t; i < 1024; i += 256)
        ((float4*)Ws)[i] = ((const float4*)W)[i];
    for (int i = t; i < rows * 64; i += 256) {
        int r = i >> 6, c = i & 63;
        Xs[r][c] = X[(size_t)(rbase + r) * 64 + c];
    }
    __syncthreads();

    int r = t & 63;
    int cg = t >> 6;            // 0..3 -> 16 columns each
    if (r < rows) {
        float acc[16];
#pragma unroll
        for (int j = 0; j < 16; j++) acc[j] = 0.0f;
#pragma unroll 8
        for (int k = 0; k < 64; k++) {
            float a = Xs[r][k];
            const float4* wr = (const float4*)(Ws + k * 64 + cg * 16);
#pragma unroll
            for (int j = 0; j < 4; j++) {
                float4 w = wr[j];
                acc[4 * j + 0] += a * w.x;
                acc[4 * j + 1] += a * w.y;
                acc[4 * j + 2] += a * w.z;
                acc[4 * j + 3] += a * w.w;
            }
        }
        float dv = g_dinv[rbase + r];
        float4* yp = (float4*)(Y + (size_t)(rbase + r) * 64 + cg * 16);
#pragma unroll
        for (int j = 0; j < 4; j++)
            yp[j] = make_float4(dv * acc[4 * j], dv * acc[4 * j + 1],
                                dv * acc[4 * j + 2], dv * acc[4 * j + 3]);
    }
}

// ---------------- GCN aggregation + bias + relu on rows [row0,row0+nr) -------
// hin rows pre-scaled by dinv. warp per row, two 16-lane groups, float4 lanes.
__global__ void agg_kernel(const float* __restrict__ hin, float* __restrict__ hout,
                           const float* __restrict__ bias, int row0, int nr) {
    int warp = (blockIdx.x * blockDim.x + threadIdx.x) >> 5;
    if (warp >= nr) return;
    int lane = threadIdx.x & 31;
    int grp  = lane >> 4;        // 0 or 1
    int fo   = lane & 15;        // float4 slot within row
    int row = row0 + warp;
    int2 oc = g_offcnt[row];
    int off = oc.x;
    int cnt = oc.y;
    float4 a0 = make_float4(0.f, 0.f, 0.f, 0.f);
    float4 a1 = make_float4(0.f, 0.f, 0.f, 0.f);
    int k = grp;
    for (; k + 2 < cnt; k += 4) {
        int c0 = __ldg(&g_col[off + k]);
        int c1 = __ldg(&g_col[off + k + 2]);
        float4 v0 = *(const float4*)(hin + (size_t)c0 * 64 + fo * 4);
        float4 v1 = *(const float4*)(hin + (size_t)c1 * 64 + fo * 4);
        a0.x += v0.x; a0.y += v0.y; a0.z += v0.z; a0.w += v0.w;
        a1.x += v1.x; a1.y += v1.y; a1.z += v1.z; a1.w += v1.w;
    }
    for (; k < cnt; k += 2) {
        int c = __ldg(&g_col[off + k]);
        float4 v = *(const float4*)(hin + (size_t)c * 64 + fo * 4);
        a0.x += v.x; a0.y += v.y; a0.z += v.z; a0.w += v.w;
    }
    if (grp == 0) {  // self loop, added once
        float4 v = *(const float4*)(hin + (size_t)row * 64 + fo * 4);
        a0.x += v.x; a0.y += v.y; a0.z += v.z; a0.w += v.w;
    }
    a0.x += a1.x; a0.y += a1.y; a0.z += a1.z; a0.w += a1.w;
    a0.x += __shfl_down_sync(0xffffffff, a0.x, 16);
    a0.y += __shfl_down_sync(0xffffffff, a0.y, 16);
    a0.z += __shfl_down_sync(0xffffffff, a0.z, 16);
    a0.w += __shfl_down_sync(0xffffffff, a0.w, 16);
    if (grp == 0) {
        float di = g_dinv[row];
        float4 b = *(const float4*)(bias + fo * 4);
        float4 o;
        o.x = fmaxf(di * a0.x + b.x, 0.f);
        o.y = fmaxf(di * a0.y + b.y, 0.f);
        o.z = fmaxf(di * a0.z + b.z, 0.f);
        o.w = fmaxf(di * a0.w + b.w, 0.f);
        *(float4*)(hout + (size_t)row * 64 + fo * 4) = o;
    }
}

// ---------------- framelet node-band weights (independent of GCN path) -------
__global__ void __launch_bounds__(1024, 1)
frame_kernel(const int* __restrict__ frow, const int* __restrict__ fcol,
             const float* __restrict__ fval, const int* __restrict__ dindex) {
    __shared__ float ws[NPG * NBANDS];   // 24 KB
    int g = blockIdx.x;
    int t = threadIdx.x;
    int node0 = g * NPG;
    for (int i = t; i < NPG * NBANDS; i += 1024) ws[i] = 0.0f;
    __syncthreads();
    int base = g * NZPG;
    for (int i = t; i < NZPG; i += 1024) {
        int k = base + i;
        int band = __ldg(&dindex[frow[k]]);
        int c = fcol[k] - node0;
        atomicAdd(&ws[c * NBANDS + band], fval[k]);
    }
    __syncthreads();
    float* dst = g_w + (size_t)g * NPG * NBANDS;
    for (int i = t; i < (NPG * NBANDS) / 4; i += 1024)
        ((float4*)dst)[i] = ((const float4*)ws)[i];
}

// ---------------- pool + MLP head (fused, one block per graph) ---------------
__global__ void __launch_bounds__(1024, 1)
tail_kernel(const float* __restrict__ h,
            const float* __restrict__ fcW1, const float* __restrict__ fcb1,
            const float* __restrict__ fcW2, const float* __restrict__ fcb2,
            float* __restrict__ out) {
    __shared__ float ws[NPG * NBANDS];         // 24 KB
    __shared__ float partial[5 * NBANDS * HH]; // 3.75 KB
    __shared__ float xs[NBANDS * HH];
    __shared__ float hid[HH];

    int g = blockIdx.x;
    int t = threadIdx.x;
    int node0 = g * NPG;

    const float* src = g_w + (size_t)g * NPG * NBANDS;
    for (int i = t; i < (NPG * NBANDS) / 4; i += 1024)
        ((float4*)ws)[i] = ((const float4*)src)[i];
    __syncthreads();

    if (t < 960) {
        int grp = t / 192;
        int p   = t % 192;
        int band = p / 64, f = p % 64;
        float acc = 0.0f;
        for (int nd = grp; nd < NPG; nd += 5)
            acc += ws[nd * NBANDS + band] * __ldg(&h[(size_t)(node0 + nd) * 64 + f]);
        partial[grp * 192 + p] = acc;
    }
    __syncthreads();
    if (t < 192) {
        xs[t] = partial[t] + partial[192 + t] + partial[384 + t]
              + partial[576 + t] + partial[768 + t];
    }
    __syncthreads();

    if (t < HH) {
        float acc = fcb1[t];
#pragma unroll 8
        for (int k = 0; k < NBANDS * HH; k++)
            acc += xs[k] * fcW1[k * HH + t];
        hid[t] = fmaxf(acc, 0.0f);
    }
    __syncthreads();
    if (t < NCC) {
        float o = fcb2[t];
#pragma unroll 8
        for (int k = 0; k < HH; k++)
            o += hid[k] * fcW2[k * NCC + t];
        out[g * NCC + t] = o;
    }
}

// ---------------- launch ----------------
extern "C" void kernel_launch(void* const* d_in, const int* in_sizes, int n_in,
                              void* d_out, int out_size) {
    const float* x         = (const float*)d_in[0];
    const int*   ei        = (const int*)  d_in[1];   // [2, E]: rows then cols
    const int*   frow      = (const int*)  d_in[3];
    const int*   fcol      = (const int*)  d_in[4];
    const float* fval      = (const float*)d_in[5];
    const int*   dindex    = (const int*)  d_in[6];
    const float* W1        = (const float*)d_in[8];
    const float* b1        = (const float*)d_in[9];
    const float* W2        = (const float*)d_in[10];
    const float* b2        = (const float*)d_in[11];
    const float* fcW1      = (const float*)d_in[12];
    const float* fcb1      = (const float*)d_in[13];
    const float* fcW2      = (const float*)d_in[14];
    const float* fcb2      = (const float*)d_in[15];
    float* out = (float*)d_out;

    const int* erow = ei;
    const int* ecol = ei + EE;

    float* bufA; cudaGetSymbolAddress((void**)&bufA, g_bufA);
    float* bufB; cudaGetSymbolAddress((void**)&bufB, g_bufB);

    bool par = g_sp.ok;
    const int AGG_BLKS  = (HALFN * 32 + 255) / 256;   // per-chain agg grid
    const int GEMM_BLKS = (HALFN + 63) / 64;          // per-chain gemm grid (782 — FIXED)

    if (par) {
        // framelet weights are input-only: run from t=0 on sC
        cudaEventRecord(g_sp.ev0, 0);
        cudaStreamWaitEvent(g_sp.sC, g_sp.ev0, 0);
        frame_kernel<<<BB, 1024, 0, g_sp.sC>>>(frow, fcol, fval, dindex);
        cudaEventRecord(g_sp.evC, g_sp.sC);

        // CSR build phase 1 (all graphs) on main
        build1_kernel<<<BB, 1024>>>(erow);
        cudaEventRecord(g_sp.evD, 0);

        // gemm1 (all rows) on sB, overlapping build2
        cudaStreamWaitEvent(g_sp.sB, g_sp.evD, 0);
        gemm64_kernel<<<(NN + 63) / 64, 256, 0, g_sp.sB>>>(x, W1, bufA, 0, NN);
        cudaEventRecord(g_sp.evB, g_sp.sB);

        build2_kernel<<<BB, 1024>>>(erow, ecol);
        cudaEventRecord(g_sp.evS, 0);

        // ---- chain A (graphs 0-24, rows [0, HALFN)) on main ----
        cudaStreamWaitEvent(0, g_sp.evB, 0);
        agg_kernel<<<AGG_BLKS, 256>>>(bufA, bufB, b1, 0, HALFN);
        gemm64_kernel<<<GEMM_BLKS, 256>>>(bufB, W2, bufA, 0, HALFN);
        agg_kernel<<<AGG_BLKS, 256>>>(bufA, bufB, b2, 0, HALFN);

        // ---- chain B (graphs 25-49, rows [HALFN, NN)) on sB ----
        cudaStreamWaitEvent(g_sp.sB, g_sp.evS, 0);
        agg_kernel<<<AGG_BLKS, 256, 0, g_sp.sB>>>(bufA, bufB, b1, HALFN, HALFN);
        gemm64_kernel<<<GEMM_BLKS, 256, 0, g_sp.sB>>>(bufB, W2, bufA, HALFN, HALFN);
        agg_kernel<<<AGG_BLKS, 256, 0, g_sp.sB>>>(bufA, bufB, b2, HALFN, HALFN);
        cudaEventRecord(g_sp.evE, g_sp.sB);

        // join both chains + framelet weights, then fused pool+head
        cudaStreamWaitEvent(0, g_sp.evE, 0);
        cudaStreamWaitEvent(0, g_sp.evC, 0);
        tail_kernel<<<BB, 1024>>>(bufB, fcW1, fcb1, fcW2, fcb2, out);
    } else {
        // serial fallback
        frame_kernel<<<BB, 1024>>>(frow, fcol, fval, dindex);
        build1_kernel<<<BB, 1024>>>(erow);
        gemm64_kernel<<<(NN + 63) / 64, 256>>>(x, W1, bufA, 0, NN);
        build2_kernel<<<BB, 1024>>>(erow, ecol);
        agg_kernel<<<(NN * 32 + 255) / 256, 256>>>(bufA, bufB, b1, 0, NN);
        gemm64_kernel<<<(NN + 63) / 64, 256>>>(bufB, W2, bufA, 0, NN);
        agg_kernel<<<(NN * 32 + 255) / 256, 256>>>(bufA, bufB, b2, 0, NN);
        tail_kernel<<<BB, 1024>>>(bufB, fcW1, fcb1, fcW2, fcb2, out);
    }
}